// round 1
// baseline (speedup 1.0000x reference)
#include <cuda_runtime.h>
#include <cuda_bf16.h>
#include <cstdint>
#include <math.h>

#define B_ROWS 4096
#define DIM    256
#define N2     8192
#define INV_T  2.0f   // 1/temperature

// Scratch (device globals; no allocations allowed)
__device__ __nv_bfloat16 g_reps[N2 * DIM];   // normalized reps, bf16 (4 MB)
__device__ float g_pair[N2];                 // sim[i, pair(i)] / T  == log(numerator_i)
__device__ float g_denom[N2];                // masked sum of exp(sim/T)

// ---------------------------------------------------------------------------
// Kernel 1: per-pair normalization + exact fp32 numerator + g_denom zeroing
// One block per i in [0,B). 256 threads = one per dim element.
// ---------------------------------------------------------------------------
__global__ void __launch_bounds__(256) norm_kernel(const float* __restrict__ emb_i,
                                                   const float* __restrict__ emb_j)
{
    int i = blockIdx.x;
    int t = threadIdx.x;

    if (blockIdx.x < 32) g_denom[blockIdx.x * 256 + t] = 0.0f;

    float a = emb_i[i * DIM + t];
    float b = emb_j[i * DIM + t];
    float sa = a * a, sb = b * b, sab = a * b;

    #pragma unroll
    for (int o = 16; o; o >>= 1) {
        sa  += __shfl_xor_sync(0xffffffffu, sa,  o);
        sb  += __shfl_xor_sync(0xffffffffu, sb,  o);
        sab += __shfl_xor_sync(0xffffffffu, sab, o);
    }
    __shared__ float red[3][8];
    int w = t >> 5, l = t & 31;
    if (l == 0) { red[0][w] = sa; red[1][w] = sb; red[2][w] = sab; }
    __syncthreads();
    sa = 0.f; sb = 0.f; sab = 0.f;
    #pragma unroll
    for (int k = 0; k < 8; k++) { sa += red[0][k]; sb += red[1][k]; sab += red[2][k]; }

    float ri = rsqrtf(sa);
    float rj = rsqrtf(sb);
    g_reps[i * DIM + t]            = __float2bfloat16(a * ri);
    g_reps[(i + B_ROWS) * DIM + t] = __float2bfloat16(b * rj);

    if (t == 0) {
        float pd = sab * ri * rj * INV_T;
        g_pair[i] = pd;
        g_pair[i + B_ROWS] = pd;
    }
}

// ---------------------------------------------------------------------------
// Kernel 2: fused GEMM (bf16 mma.sync, fp32 accum) + exp + mask + row/col sums.
// Only upper-triangular 128x128 tiles (bm <= bn); off-diagonal tiles scatter
// both row sums and (by symmetry) column sums. 2080 CTAs, 256 thr (8 warps).
// Warp tile: 64 rows x 32 cols, via m16n8k16.
// ---------------------------------------------------------------------------
__global__ void __launch_bounds__(256, 2) sim_kernel(const int* __restrict__ tags,
                                                     const int* __restrict__ docs)
{
    // linear block -> (bm, bn) with bm <= bn
    int p = blockIdx.x, bm = 0;
    while (p >= 64 - bm) { p -= 64 - bm; bm++; }
    int bn = bm + p;

    __shared__ __align__(16) __nv_bfloat16 As[128][72];
    __shared__ __align__(16) __nv_bfloat16 Bs[128][72];
    __shared__ int rtag[128], ctag[128], rdoc[128], cdoc[128];
    __shared__ float rowsum[128], colsum[128];

    int t    = threadIdx.x;
    int lane = t & 31;
    int wid  = t >> 5;
    int wm   = wid >> 2;   // 0..1  (row half)
    int wn   = wid & 3;    // 0..3  (col quarter)

    if (t < 128) {
        rowsum[t] = 0.f; colsum[t] = 0.f;
        int gr = bm * 128 + t, gc = bn * 128 + t;
        rtag[t] = tags[gr & (B_ROWS - 1)];
        rdoc[t] = docs[gr & (B_ROWS - 1)];
        ctag[t] = tags[gc & (B_ROWS - 1)];
        cdoc[t] = docs[gc & (B_ROWS - 1)];
    }

    float acc[4][4][4];
    #pragma unroll
    for (int a = 0; a < 4; a++)
        #pragma unroll
        for (int b = 0; b < 4; b++)
            #pragma unroll
            for (int c = 0; c < 4; c++) acc[a][b][c] = 0.f;

    // ldmatrix lane-address components
    int a_row = (lane & 7) + (lane & 8);            // 0..15
    int a_k8  = (lane & 16) ? 8 : 0;
    int b_row = (lane & 7) + ((lane & 16) ? 8 : 0); // 0..15
    int b_k8  = (lane & 8) ? 8 : 0;

    int lr = t >> 3;           // smem fill: row 0..31 (+32*it)
    int lc = (t & 7) * 8;      // smem fill: bf16 col offset

    for (int kc = 0; kc < 4; kc++) {                // K chunks of 64
        __syncthreads();
        #pragma unroll
        for (int it = 0; it < 4; it++) {
            int r = lr + 32 * it;
            uint4 va = ((const uint4*)g_reps)[(size_t)(bm * 128 + r) * 32 + kc * 8 + (t & 7)];
            *(uint4*)&As[r][lc] = va;
            uint4 vb = ((const uint4*)g_reps)[(size_t)(bn * 128 + r) * 32 + kc * 8 + (t & 7)];
            *(uint4*)&Bs[r][lc] = vb;
        }
        __syncthreads();

        #pragma unroll
        for (int ks = 0; ks < 4; ks++) {            // k steps of 16
            uint32_t af[4][4];
            #pragma unroll
            for (int mf = 0; mf < 4; mf++) {
                int row = wm * 64 + mf * 16 + a_row;
                int col = ks * 16 + a_k8;
                uint32_t addr = (uint32_t)__cvta_generic_to_shared(&As[row][col]);
                asm volatile("ldmatrix.sync.aligned.m8n8.x4.shared.b16 {%0,%1,%2,%3}, [%4];"
                    : "=r"(af[mf][0]), "=r"(af[mf][1]), "=r"(af[mf][2]), "=r"(af[mf][3])
                    : "r"(addr));
            }
            uint32_t bfr[4][2];
            #pragma unroll
            for (int nf2 = 0; nf2 < 2; nf2++) {
                int row = wn * 32 + nf2 * 16 + b_row;
                int col = ks * 16 + b_k8;
                uint32_t addr = (uint32_t)__cvta_generic_to_shared(&Bs[row][col]);
                asm volatile("ldmatrix.sync.aligned.m8n8.x4.shared.b16 {%0,%1,%2,%3}, [%4];"
                    : "=r"(bfr[nf2*2][0]), "=r"(bfr[nf2*2][1]),
                      "=r"(bfr[nf2*2+1][0]), "=r"(bfr[nf2*2+1][1])
                    : "r"(addr));
            }
            #pragma unroll
            for (int mf = 0; mf < 4; mf++)
                #pragma unroll
                for (int nf = 0; nf < 4; nf++)
                    asm volatile(
                        "mma.sync.aligned.m16n8k16.row.col.f32.bf16.bf16.f32 "
                        "{%0,%1,%2,%3},{%4,%5,%6,%7},{%8,%9},{%0,%1,%2,%3};"
                        : "+f"(acc[mf][nf][0]), "+f"(acc[mf][nf][1]),
                          "+f"(acc[mf][nf][2]), "+f"(acc[mf][nf][3])
                        : "r"(af[mf][0]), "r"(af[mf][1]), "r"(af[mf][2]), "r"(af[mf][3]),
                          "r"(bfr[nf][0]), "r"(bfr[nf][1]));
        }
    }

    // ---------------- Epilogue: exp + mask + row/col sums -------------------
    float colacc[4][2];
    #pragma unroll
    for (int nf = 0; nf < 4; nf++) { colacc[nf][0] = 0.f; colacc[nf][1] = 0.f; }

    #pragma unroll
    for (int mf = 0; mf < 4; mf++) {
        int r0l = wm * 64 + mf * 16 + (lane >> 2);
        int r1l = r0l + 8;
        int tg0 = rtag[r0l], dc0 = rdoc[r0l];
        int tg1 = rtag[r1l], dc1 = rdoc[r1l];
        float rs0 = 0.f, rs1 = 0.f;
        #pragma unroll
        for (int nf = 0; nf < 4; nf++) {
            int c0l = wn * 32 + nf * 8 + (lane & 3) * 2;
            int ct0 = ctag[c0l], cd0 = cdoc[c0l];
            int ct1 = ctag[c0l + 1], cd1 = cdoc[c0l + 1];
            float v00 = (tg0 != ct0 && dc0 != cd0) ? __expf(INV_T * acc[mf][nf][0]) : 0.f;
            float v01 = (tg0 != ct1 && dc0 != cd1) ? __expf(INV_T * acc[mf][nf][1]) : 0.f;
            float v10 = (tg1 != ct0 && dc1 != cd0) ? __expf(INV_T * acc[mf][nf][2]) : 0.f;
            float v11 = (tg1 != ct1 && dc1 != cd1) ? __expf(INV_T * acc[mf][nf][3]) : 0.f;
            rs0 += v00 + v01;
            rs1 += v10 + v11;
            colacc[nf][0] += v00 + v10;
            colacc[nf][1] += v01 + v11;
        }
        rs0 += __shfl_xor_sync(0xffffffffu, rs0, 1);
        rs0 += __shfl_xor_sync(0xffffffffu, rs0, 2);
        rs1 += __shfl_xor_sync(0xffffffffu, rs1, 1);
        rs1 += __shfl_xor_sync(0xffffffffu, rs1, 2);
        if ((lane & 3) == 0) {
            atomicAdd(&rowsum[r0l], rs0);
            atomicAdd(&rowsum[r1l], rs1);
        }
    }

    if (bm != bn) {
        #pragma unroll
        for (int nf = 0; nf < 4; nf++) {
            float c0 = colacc[nf][0], c1 = colacc[nf][1];
            c0 += __shfl_xor_sync(0xffffffffu, c0, 4);
            c0 += __shfl_xor_sync(0xffffffffu, c0, 8);
            c0 += __shfl_xor_sync(0xffffffffu, c0, 16);
            c1 += __shfl_xor_sync(0xffffffffu, c1, 4);
            c1 += __shfl_xor_sync(0xffffffffu, c1, 8);
            c1 += __shfl_xor_sync(0xffffffffu, c1, 16);
            if (lane < 4) {
                int c = wn * 32 + nf * 8 + lane * 2;
                atomicAdd(&colsum[c], c0);
                atomicAdd(&colsum[c + 1], c1);
            }
        }
    }
    __syncthreads();

    if (t < 128) {
        atomicAdd(&g_denom[bm * 128 + t], rowsum[t]);
        if (bm != bn) atomicAdd(&g_denom[bn * 128 + t], colsum[t]);
    }
}

// ---------------------------------------------------------------------------
// Kernel 3: loss = mean over rows of ( log(denom + 0.1) - log(numerator) )
// ---------------------------------------------------------------------------
__global__ void __launch_bounds__(256) loss_kernel(float* __restrict__ out)
{
    int t = threadIdx.x;
    float s = 0.f;
    for (int r = t; r < N2; r += 256)
        s += logf(g_denom[r] + 0.1f) - g_pair[r];

    #pragma unroll
    for (int o = 16; o; o >>= 1) s += __shfl_xor_sync(0xffffffffu, s, o);

    __shared__ float red[8];
    if ((t & 31) == 0) red[t >> 5] = s;
    __syncthreads();
    if (t == 0) {
        float tot = 0.f;
        #pragma unroll
        for (int k = 0; k < 8; k++) tot += red[k];
        out[0] = tot / (float)N2;
    }
}

// ---------------------------------------------------------------------------
extern "C" void kernel_launch(void* const* d_in, const int* in_sizes, int n_in,
                              void* d_out, int out_size)
{
    const float* emb_i = (const float*)d_in[0];
    const float* emb_j = (const float*)d_in[1];
    const int*   tags  = (const int*)d_in[2];
    const int*   docs  = (const int*)d_in[n_in - 1];  // document_ids (num_classes at [3])

    norm_kernel<<<B_ROWS, 256>>>(emb_i, emb_j);
    sim_kernel<<<2080, 256>>>(tags, docs);            // 64*65/2 upper-tri tiles
    loss_kernel<<<1, 256>>>((float*)d_out);
}

// round 3
// speedup vs baseline: 1.1361x; 1.1361x over previous
#include <cuda_runtime.h>
#include <cuda_bf16.h>
#include <cstdint>
#include <math.h>

#define B_ROWS 4096
#define DIM    256
#define N2     8192

// Scratch (device globals; allocations forbidden)
__device__ __nv_bfloat16 g_reps[N2 * DIM];   // normalized reps, bf16 (4 MB)
__device__ float g_pair[N2];                 // sim[i,pair(i)]/T == log(numerator)
__device__ float g_denom[N2];                // masked sum of exp(sim/T)

__device__ __forceinline__ uint32_t smem_u32(const void* p) {
    return (uint32_t)__cvta_generic_to_shared(p);
}

// ---------------------------------------------------------------------------
// Kernel 1: normalization. Warp-per-row, shuffle-only reductions.
// 512 blocks x 256 threads; 8 rows/block.
// ---------------------------------------------------------------------------
__global__ void __launch_bounds__(256) norm_kernel(const float* __restrict__ emb_i,
                                                   const float* __restrict__ emb_j)
{
    int t = threadIdx.x, lane = t & 31, w = t >> 5;
    int gid = blockIdx.x * 256 + t;
    if (gid < N2) g_denom[gid] = 0.0f;

    int row = blockIdx.x * 8 + w;    // 0..4095
    const float4* ai = (const float4*)emb_i + (size_t)row * 64;
    const float4* bj = (const float4*)emb_j + (size_t)row * 64;
    float4 a0 = ai[lane], a1 = ai[32 + lane];
    float4 b0 = bj[lane], b1 = bj[32 + lane];

    float sa = a0.x*a0.x + a0.y*a0.y + a0.z*a0.z + a0.w*a0.w
             + a1.x*a1.x + a1.y*a1.y + a1.z*a1.z + a1.w*a1.w;
    float sb = b0.x*b0.x + b0.y*b0.y + b0.z*b0.z + b0.w*b0.w
             + b1.x*b1.x + b1.y*b1.y + b1.z*b1.z + b1.w*b1.w;
    float sab = a0.x*b0.x + a0.y*b0.y + a0.z*b0.z + a0.w*b0.w
              + a1.x*b1.x + a1.y*b1.y + a1.z*b1.z + a1.w*b1.w;
    #pragma unroll
    for (int o = 16; o; o >>= 1) {
        sa  += __shfl_xor_sync(0xffffffffu, sa,  o);
        sb  += __shfl_xor_sync(0xffffffffu, sb,  o);
        sab += __shfl_xor_sync(0xffffffffu, sab, o);
    }
    float ri = rsqrtf(sa), rj = rsqrtf(sb);

    __nv_bfloat162 p0 = __floats2bfloat162_rn(a0.x*ri, a0.y*ri);
    __nv_bfloat162 p1 = __floats2bfloat162_rn(a0.z*ri, a0.w*ri);
    __nv_bfloat162 p2 = __floats2bfloat162_rn(a1.x*ri, a1.y*ri);
    __nv_bfloat162 p3 = __floats2bfloat162_rn(a1.z*ri, a1.w*ri);
    uint2* outA = (uint2*)g_reps + (size_t)row * 64;
    outA[lane]      = make_uint2(*(uint32_t*)&p0, *(uint32_t*)&p1);
    outA[32 + lane] = make_uint2(*(uint32_t*)&p2, *(uint32_t*)&p3);

    __nv_bfloat162 q0 = __floats2bfloat162_rn(b0.x*rj, b0.y*rj);
    __nv_bfloat162 q1 = __floats2bfloat162_rn(b0.z*rj, b0.w*rj);
    __nv_bfloat162 q2 = __floats2bfloat162_rn(b1.x*rj, b1.y*rj);
    __nv_bfloat162 q3 = __floats2bfloat162_rn(b1.z*rj, b1.w*rj);
    uint2* outB = (uint2*)g_reps + (size_t)(row + B_ROWS) * 64;
    outB[lane]      = make_uint2(*(uint32_t*)&q0, *(uint32_t*)&q1);
    outB[32 + lane] = make_uint2(*(uint32_t*)&q2, *(uint32_t*)&q3);

    if (lane == 0) {
        float pd = sab * ri * rj * 2.0f;   // /T with T=0.5
        g_pair[row] = pd;
        g_pair[row + B_ROWS] = pd;
    }
}

// ---------------------------------------------------------------------------
// Kernel 2: bf16 mma.sync GEMM, cp.async double-buffered, fused epilogue.
// Upper-triangular 128x128 tiles (bm<=bn); off-diagonal tiles also scatter
// column sums (symmetry). 2080 CTAs, 256 threads (8 warps), 2 CTAs/SM.
// K = 256 in 4 chunks of 64, 2 chunks in flight.
// ---------------------------------------------------------------------------
#define CH_BYTES 18432   // 128 rows * 72 bf16 * 2B

__global__ void __launch_bounds__(256, 2) sim_kernel(const int* __restrict__ tags,
                                                     const int* __restrict__ docs)
{
    extern __shared__ __align__(16) char dsm[];
    // buffers: A0 A1 B0 B1, each [128][72] bf16 (pad 72 keeps ldmatrix conflict-free)
    uint32_t A_s[2] = { smem_u32(dsm),                smem_u32(dsm) + CH_BYTES };
    uint32_t B_s[2] = { smem_u32(dsm) + 2*CH_BYTES,   smem_u32(dsm) + 3*CH_BYTES };
    __nv_bfloat16* Agen[2] = { (__nv_bfloat16*)dsm,
                               (__nv_bfloat16*)(dsm + CH_BYTES) };
    __nv_bfloat16* Bgen[2] = { (__nv_bfloat16*)(dsm + 2*CH_BYTES),
                               (__nv_bfloat16*)(dsm + 3*CH_BYTES) };

    __shared__ uint32_t rkey[128], ckey[128];
    __shared__ float rowsum[128], colsum[128];

    int t    = threadIdx.x;
    int lane = t & 31;
    int wid  = t >> 5;
    int wm   = wid >> 2;   // 0..1  (row half)
    int wn   = wid & 3;    // 0..3  (col quarter)

    // linear block -> (bm, bn), bm <= bn
    int p = blockIdx.x, bm = 0;
    while (p >= 64 - bm) { p -= 64 - bm; bm++; }
    int bn = bm + p;
    int row0 = bm * 128, col0 = bn * 128;
    bool offd = (bm != bn);

    if (t < 128) {
        rowsum[t] = 0.f; colsum[t] = 0.f;
        int gr = (row0 + t) & (B_ROWS - 1);
        int gc = (col0 + t) & (B_ROWS - 1);
        rkey[t] = ((uint32_t)tags[gr] << 16) | (uint32_t)docs[gr];
        ckey[t] = ((uint32_t)tags[gc] << 16) | (uint32_t)docs[gc];
    }

    // cp.async fill lambda-ish macro: each thread moves 4x16B for A and B
    // v = t + 256*i (0..1023): row r = v>>3, vec c = v&7 (16B units of 128B row)
    #define FILL_CHUNK(kc, buf)                                                        \
    {                                                                                  \
        int _kc = (kc);                                                                \
        _Pragma("unroll")                                                              \
        for (int i = 0; i < 4; i++) {                                                  \
            int v = t + 256 * i;                                                       \
            int r = v >> 3, c = v & 7;                                                 \
            uint32_t off = (uint32_t)(r * 144 + c * 16);                               \
            const __nv_bfloat16* sA = g_reps + (size_t)(row0 + r) * DIM + _kc * 64 + c * 8; \
            const __nv_bfloat16* sB = g_reps + (size_t)(col0 + r) * DIM + _kc * 64 + c * 8; \
            asm volatile("cp.async.cg.shared.global [%0], [%1], 16;"                   \
                         :: "r"(A_s[buf] + off), "l"(sA) : "memory");                  \
            asm volatile("cp.async.cg.shared.global [%0], [%1], 16;"                   \
                         :: "r"(B_s[buf] + off), "l"(sB) : "memory");                  \
        }                                                                              \
        asm volatile("cp.async.commit_group;" ::: "memory");                           \
    }

    float acc[4][4][4];
    #pragma unroll
    for (int a = 0; a < 4; a++)
        #pragma unroll
        for (int b = 0; b < 4; b++)
            #pragma unroll
            for (int c = 0; c < 4; c++) acc[a][b][c] = 0.f;

    // ldmatrix lane-address components
    int a_row = (lane & 7) + (lane & 8);            // 0..15
    int a_k8  = (lane & 16) ? 8 : 0;
    int b_row = (lane & 7) + ((lane & 16) ? 8 : 0); // 0..15
    int b_k8  = (lane & 8) ? 8 : 0;

    FILL_CHUNK(0, 0);
    FILL_CHUNK(1, 1);

    #pragma unroll
    for (int kc = 0; kc < 4; kc++) {                // K chunks of 64
        if (kc < 3)
            asm volatile("cp.async.wait_group 1;" ::: "memory");
        else
            asm volatile("cp.async.wait_group 0;" ::: "memory");
        __syncthreads();

        int buf = kc & 1;
        __nv_bfloat16* Ab = Agen[buf];
        __nv_bfloat16* Bb = Bgen[buf];

        #pragma unroll
        for (int ks = 0; ks < 4; ks++) {            // k steps of 16
            uint32_t af[4][4];
            #pragma unroll
            for (int mf = 0; mf < 4; mf++) {
                int row = wm * 64 + mf * 16 + a_row;
                int col = ks * 16 + a_k8;
                uint32_t addr = smem_u32(Ab + row * 72 + col);
                asm volatile("ldmatrix.sync.aligned.m8n8.x4.shared.b16 {%0,%1,%2,%3}, [%4];"
                    : "=r"(af[mf][0]), "=r"(af[mf][1]), "=r"(af[mf][2]), "=r"(af[mf][3])
                    : "r"(addr));
            }
            uint32_t bfr[4][2];
            #pragma unroll
            for (int nf2 = 0; nf2 < 2; nf2++) {
                int row = wn * 32 + nf2 * 16 + b_row;
                int col = ks * 16 + b_k8;
                uint32_t addr = smem_u32(Bb + row * 72 + col);
                asm volatile("ldmatrix.sync.aligned.m8n8.x4.shared.b16 {%0,%1,%2,%3}, [%4];"
                    : "=r"(bfr[nf2*2][0]), "=r"(bfr[nf2*2][1]),
                      "=r"(bfr[nf2*2+1][0]), "=r"(bfr[nf2*2+1][1])
                    : "r"(addr));
            }
            #pragma unroll
            for (int mf = 0; mf < 4; mf++)
                #pragma unroll
                for (int nf = 0; nf < 4; nf++)
                    asm volatile(
                        "mma.sync.aligned.m16n8k16.row.col.f32.bf16.bf16.f32 "
                        "{%0,%1,%2,%3},{%4,%5,%6,%7},{%8,%9},{%0,%1,%2,%3};"
                        : "+f"(acc[mf][nf][0]), "+f"(acc[mf][nf][1]),
                          "+f"(acc[mf][nf][2]), "+f"(acc[mf][nf][3])
                        : "r"(af[mf][0]), "r"(af[mf][1]), "r"(af[mf][2]), "r"(af[mf][3]),
                          "r"(bfr[nf][0]), "r"(bfr[nf][1]));
        }

        if (kc < 2) {
            __syncthreads();            // all warps done reading buf before refill
            FILL_CHUNK(kc + 2, buf);
        }
    }
    #undef FILL_CHUNK

    // ---------------- Epilogue: exp + mask + row/col sums -------------------
    float colacc[4][2];
    #pragma unroll
    for (int nf = 0; nf < 4; nf++) { colacc[nf][0] = 0.f; colacc[nf][1] = 0.f; }

    #pragma unroll
    for (int mf = 0; mf < 4; mf++) {
        int r0l = wm * 64 + mf * 16 + (lane >> 2);
        int r1l = r0l + 8;
        uint32_t rk0 = rkey[r0l], rk1 = rkey[r1l];
        float rs0 = 0.f, rs1 = 0.f;
        #pragma unroll
        for (int nf = 0; nf < 4; nf++) {
            int c0l = wn * 32 + nf * 8 + (lane & 3) * 2;
            uint32_t ck0 = ckey[c0l], ck1 = ckey[c0l + 1];
            uint32_t x00 = rk0 ^ ck0, x01 = rk0 ^ ck1;
            uint32_t x10 = rk1 ^ ck0, x11 = rk1 ^ ck1;
            float v00 = ((x00 >> 16) && (x00 & 0xffffu)) ? __expf(2.0f * acc[mf][nf][0]) : 0.f;
            float v01 = ((x01 >> 16) && (x01 & 0xffffu)) ? __expf(2.0f * acc[mf][nf][1]) : 0.f;
            float v10 = ((x10 >> 16) && (x10 & 0xffffu)) ? __expf(2.0f * acc[mf][nf][2]) : 0.f;
            float v11 = ((x11 >> 16) && (x11 & 0xffffu)) ? __expf(2.0f * acc[mf][nf][3]) : 0.f;
            rs0 += v00 + v01;
            rs1 += v10 + v11;
            colacc[nf][0] += v00 + v10;
            colacc[nf][1] += v01 + v11;
        }
        rs0 += __shfl_xor_sync(0xffffffffu, rs0, 1);
        rs0 += __shfl_xor_sync(0xffffffffu, rs0, 2);
        rs1 += __shfl_xor_sync(0xffffffffu, rs1, 1);
        rs1 += __shfl_xor_sync(0xffffffffu, rs1, 2);
        if ((lane & 3) == 0) {
            atomicAdd(&rowsum[r0l], rs0);
            atomicAdd(&rowsum[r1l], rs1);
        }
    }

    if (offd) {
        #pragma unroll
        for (int nf = 0; nf < 4; nf++) {
            float c0 = colacc[nf][0], c1 = colacc[nf][1];
            c0 += __shfl_xor_sync(0xffffffffu, c0, 4);
            c0 += __shfl_xor_sync(0xffffffffu, c0, 8);
            c0 += __shfl_xor_sync(0xffffffffu, c0, 16);
            c1 += __shfl_xor_sync(0xffffffffu, c1, 4);
            c1 += __shfl_xor_sync(0xffffffffu, c1, 8);
            c1 += __shfl_xor_sync(0xffffffffu, c1, 16);
            if (lane < 4) {
                int c = wn * 32 + nf * 8 + lane * 2;
                atomicAdd(&colsum[c], c0);
                atomicAdd(&colsum[c + 1], c1);
            }
        }
    }
    __syncthreads();

    if (t < 128) {
        atomicAdd(&g_denom[row0 + t], rowsum[t]);
        if (offd) atomicAdd(&g_denom[col0 + t], colsum[t]);
    }
}

// ---------------------------------------------------------------------------
// Kernel 3: loss = mean( log(denom + 0.1) - log(numerator) )
// ---------------------------------------------------------------------------
__global__ void __launch_bounds__(1024) loss_kernel(float* __restrict__ out)
{
    int t = threadIdx.x;
    float s = 0.f;
    #pragma unroll
    for (int r = t; r < N2; r += 1024)
        s += __logf(g_denom[r] + 0.1f) - g_pair[r];

    #pragma unroll
    for (int o = 16; o; o >>= 1) s += __shfl_xor_sync(0xffffffffu, s, o);

    __shared__ float red[32];
    if ((t & 31) == 0) red[t >> 5] = s;
    __syncthreads();
    if (t == 0) {
        float tot = 0.f;
        #pragma unroll
        for (int k = 0; k < 32; k++) tot += red[k];
        out[0] = tot / (float)N2;
    }
}

// ---------------------------------------------------------------------------
#define SIM_DSMEM (4 * CH_BYTES)   // 73728 B

extern "C" void kernel_launch(void* const* d_in, const int* in_sizes, int n_in,
                              void* d_out, int out_size)
{
    const float* emb_i = (const float*)d_in[0];
    const float* emb_j = (const float*)d_in[1];
    const int*   tags  = (const int*)d_in[2];
    const int*   docs  = (const int*)d_in[n_in - 1];

    cudaFuncSetAttribute(sim_kernel, cudaFuncAttributeMaxDynamicSharedMemorySize, SIM_DSMEM);

    norm_kernel<<<512, 256>>>(emb_i, emb_j);
    sim_kernel<<<2080, 256, SIM_DSMEM>>>(tags, docs);
    loss_kernel<<<1, 1024>>>((float*)d_out);
}